// round 2
// baseline (speedup 1.0000x reference)
#include <cuda_runtime.h>

#define Nn 50000
#define Mm 24
#define FN 92
#define FE 41
#define Ff 64
#define Cc 128

typedef unsigned long long ull;

// ---- scratch (static device globals; no allocation) ----
__device__ float g_bufA[Nn * Ff];          // 12.8 MB
__device__ float g_bufB[Nn * Ff];          // 12.8 MB
__device__ float g_S[(size_t)Nn * Cc];     // 25.6 MB
__device__ float g_P[(size_t)Nn * Cc];     // 25.6 MB
__device__ float g_U[3 * FE * Cc];         // folded edge weights
__device__ float g_dv[3 * Cc];             // folded edge bias

// ---- f32x2 packed helpers ----
__device__ __forceinline__ ull pack_dup(float x) {
    ull r; asm("mov.b64 %0, {%1, %1};" : "=l"(r) : "f"(x)); return r;
}
__device__ __forceinline__ ull pack2(float x, float y) {
    ull r; asm("mov.b64 %0, {%1, %2};" : "=l"(r) : "f"(x), "f"(y)); return r;
}
__device__ __forceinline__ void unpack2(ull v, float& x, float& y) {
    asm("mov.b64 {%0, %1}, %2;" : "=f"(x), "=f"(y) : "l"(v));
}
__device__ __forceinline__ void fma2(ull& acc, ull a, ull b) {
    asm("fma.rn.f32x2 %0, %1, %2, %0;" : "+l"(acc) : "l"(a), "l"(b));
}

// ---- fast activations (MUFU) ----
__device__ __forceinline__ float ex2_(float x) { float r; asm("ex2.approx.f32 %0, %1;" : "=f"(r) : "f"(x)); return r; }
__device__ __forceinline__ float lg2_(float x) { float r; asm("lg2.approx.f32 %0, %1;" : "=f"(r) : "f"(x)); return r; }
__device__ __forceinline__ float rcp_(float x) { float r; asm("rcp.approx.f32 %0, %1;" : "=f"(r) : "f"(x)); return r; }

__device__ __forceinline__ float sigmoidf_(float x) {
    // 1/(1+2^(-x*log2e)); ex2(+inf)->inf, rcp(inf)->0: safe at extremes
    return rcp_(1.0f + ex2_(-1.4426950408889634f * x));
}
__device__ __forceinline__ float softplusf_(float x) {
    // max(x,0) + ln2*log2(1 + 2^(-|x|*log2e)) ; overflow-free
    float a = fabsf(x);
    float e = ex2_(-1.4426950408889634f * a);
    return fmaf(lg2_(1.0f + e), 0.6931471805599453f, fmaxf(x, 0.0f));
}

// ---- kernel 1: node0 = node_fea @ Wn + bn ----
__global__ void __launch_bounds__(256) k_node_in(const float* __restrict__ nf,
                                                 const float* __restrict__ Wn,
                                                 const float* __restrict__ bn) {
    __shared__ float s_nf[8 * FN];
    int nbase = blockIdx.x * 8;
    for (int i = threadIdx.x; i < 8 * FN; i += 256)
        s_nf[i] = nf[(size_t)nbase * FN + i];
    __syncthreads();
    int g = threadIdx.x >> 5, c = threadIdx.x & 31;
    ull acc = pack2(bn[2 * c], bn[2 * c + 1]);
    const float* nr = &s_nf[g * FN];
#pragma unroll 4
    for (int k = 0; k < FN; k++) {
        ull w = *(const ull*)&Wn[k * Ff + 2 * c];
        fma2(acc, pack_dup(nr[k]), w);
    }
    *(ull*)&g_bufA[(size_t)(nbase + g) * Ff + 2 * c] = acc;
}

// ---- kernel 2: fold U_l = We @ W_l[128:192,:],  dv_l = be @ W_l[128:192,:] ----
__global__ void __launch_bounds__(128) k_fold(const float* __restrict__ We,
                                              const float* __restrict__ be,
                                              const float* __restrict__ W1,
                                              const float* __restrict__ W2,
                                              const float* __restrict__ W3) {
    int l = blockIdx.x;
    const float* W = (l == 0) ? W1 : ((l == 1) ? W2 : W3);
    int c = threadIdx.x;  // 0..127
    for (int r = 0; r < FE; r++) {
        float u = 0.0f;
#pragma unroll 8
        for (int k = 0; k < Ff; k++)
            u = fmaf(We[r * Ff + k], W[(size_t)(128 + k) * Cc + c], u);
        g_U[(l * FE + r) * Cc + c] = u;
    }
    float dv = 0.0f;
#pragma unroll 8
    for (int k = 0; k < Ff; k++)
        dv = fmaf(be[k], W[(size_t)(128 + k) * Cc + c], dv);
    g_dv[l * Cc + c] = dv;
}

// ---- kernel 3: per-layer S/P precompute ----
// S[n] = node[n] @ W[0:64]   + b + dv
// P[n] = node[n] @ W[64:128]
__global__ void __launch_bounds__(256) k_SP(int srcSel, const float* __restrict__ W,
                                            const float* __restrict__ b, int l) {
    const float* node = srcSel ? g_bufB : g_bufA;
    __shared__ float s_nT[64 * 16];  // [k][node_local]
    int nbase = blockIdx.x * 16;
    for (int i = threadIdx.x; i < 1024; i += 256) {
        int k = i & 63, nl = i >> 6;
        s_nT[k * 16 + nl] = node[(size_t)(nbase + nl) * 64 + k];
    }
    __syncthreads();
    int c = threadIdx.x & 63, gq = threadIdx.x >> 6;  // c = column-pair idx
    float2 bv = ((const float2*)b)[c];
    float2 dv = ((const float2*)(g_dv + l * Cc))[c];
    ull s0 = pack2(bv.x + dv.x, bv.y + dv.y);
    ull s1 = s0, s2 = s0, s3 = s0;
    ull p0 = 0, p1 = 0, p2 = 0, p3 = 0;
#pragma unroll 4
    for (int k = 0; k < 64; k++) {
        ull wS = *(const ull*)&W[(size_t)k * Cc + 2 * c];
        ull wP = *(const ull*)&W[(size_t)(64 + k) * Cc + 2 * c];
        float4 nv = *(const float4*)&s_nT[k * 16 + gq * 4];
        ull b0 = pack_dup(nv.x); fma2(s0, b0, wS); fma2(p0, b0, wP);
        ull b1 = pack_dup(nv.y); fma2(s1, b1, wS); fma2(p1, b1, wP);
        ull b2 = pack_dup(nv.z); fma2(s2, b2, wS); fma2(p2, b2, wP);
        ull b3 = pack_dup(nv.w); fma2(s3, b3, wS); fma2(p3, b3, wP);
    }
    int n0 = nbase + gq * 4;
    *(ull*)&g_S[(size_t)(n0 + 0) * Cc + 2 * c] = s0;
    *(ull*)&g_S[(size_t)(n0 + 1) * Cc + 2 * c] = s1;
    *(ull*)&g_S[(size_t)(n0 + 2) * Cc + 2 * c] = s2;
    *(ull*)&g_S[(size_t)(n0 + 3) * Cc + 2 * c] = s3;
    *(ull*)&g_P[(size_t)(n0 + 0) * Cc + 2 * c] = p0;
    *(ull*)&g_P[(size_t)(n0 + 1) * Cc + 2 * c] = p1;
    *(ull*)&g_P[(size_t)(n0 + 2) * Cc + 2 * c] = p2;
    *(ull*)&g_P[(size_t)(n0 + 3) * Cc + 2 * c] = p3;
}

// ---- kernel 4: fused conv layer ----
// gated[n,m] = S[n] + P[idx[n,m]] + ef[n,m] @ U
// out[n] = softplus(alpha*node[n] + sum_m mask*sigmoid(g_f)*softplus(g_c))
__global__ void __launch_bounds__(128, 4) k_conv(int srcSel, int dstSel,
                                                 const float* __restrict__ ef,
                                                 const int* __restrict__ idx,
                                                 const float* __restrict__ alpha_p,
                                                 float* __restrict__ outp, int l) {
    const float* nodein = srcSel ? g_bufB : g_bufA;
    float* dst = (dstSel == 0) ? g_bufA : ((dstSel == 1) ? g_bufB : outp);

    __shared__ __align__(16) float s_U[FE * Cc];       // 21 KB
    __shared__ __align__(16) float s_ef[4 * FE * 24];  // 15.7 KB transposed [g][r][m]
    __shared__ int s_idx[4 * 24];

    int tid = threadIdx.x;
    const float* Ul = g_U + l * FE * Cc;
    for (int i = tid; i < FE * Cc; i += 128) s_U[i] = Ul[i];
    int nbase = blockIdx.x * 4;
    for (int i = tid; i < 4 * 24 * FE; i += 128) {
        int g = i / (24 * FE);
        int rem = i - g * 24 * FE;
        int m = rem / FE;
        int r = rem - m * FE;
        s_ef[(g * FE + r) * 24 + m] = ef[(size_t)nbase * 24 * FE + i];
    }
    for (int i = tid; i < 96; i += 128) s_idx[i] = idx[(size_t)nbase * 24 + i];
    __syncthreads();

    int g = tid >> 5, j = tid & 31;  // j = feature-pair index (cols 2j,2j+1)
    int n = nbase + g;
    float2 Sf = *(const float2*)&g_S[(size_t)n * Cc + 2 * j];
    float2 Sc = *(const float2*)&g_S[(size_t)n * Cc + 64 + 2 * j];
    float accx = 0.0f, accy = 0.0f;
    float alpha = alpha_p[0];
    const float* efg = &s_ef[g * FE * 24];

#pragma unroll 1
    for (int mb = 0; mb < 3; mb++) {  // 3 blocks of 8 edges
        ull qf[8], qc[8];
#pragma unroll
        for (int mm = 0; mm < 8; mm++) { qf[mm] = 0ULL; qc[mm] = 0ULL; }
#pragma unroll 4
        for (int r = 0; r < FE; r++) {
            float4 e0 = *(const float4*)&efg[r * 24 + mb * 8];
            float4 e1 = *(const float4*)&efg[r * 24 + mb * 8 + 4];
            ull uf = *(const ull*)&s_U[r * Cc + 2 * j];
            ull uc = *(const ull*)&s_U[r * Cc + 64 + 2 * j];
            ull bb;
            bb = pack_dup(e0.x); fma2(qf[0], bb, uf); fma2(qc[0], bb, uc);
            bb = pack_dup(e0.y); fma2(qf[1], bb, uf); fma2(qc[1], bb, uc);
            bb = pack_dup(e0.z); fma2(qf[2], bb, uf); fma2(qc[2], bb, uc);
            bb = pack_dup(e0.w); fma2(qf[3], bb, uf); fma2(qc[3], bb, uc);
            bb = pack_dup(e1.x); fma2(qf[4], bb, uf); fma2(qc[4], bb, uc);
            bb = pack_dup(e1.y); fma2(qf[5], bb, uf); fma2(qc[5], bb, uc);
            bb = pack_dup(e1.z); fma2(qf[6], bb, uf); fma2(qc[6], bb, uc);
            bb = pack_dup(e1.w); fma2(qf[7], bb, uf); fma2(qc[7], bb, uc);
        }
#pragma unroll
        for (int mm = 0; mm < 8; mm++) {
            int ii = s_idx[g * 24 + mb * 8 + mm];
            int iv = (ii < 0) ? 0 : ii;
            const float* Pr = &g_P[(size_t)iv * Cc];
            float2 Pf = *(const float2*)&Pr[2 * j];
            float2 Pc = *(const float2*)&Pr[64 + 2 * j];
            float qfx, qfy, qcx, qcy;
            unpack2(qf[mm], qfx, qfy);
            unpack2(qc[mm], qcx, qcy);
            float gfx = Sf.x + Pf.x + qfx;
            float gfy = Sf.y + Pf.y + qfy;
            float gcx = Sc.x + Pc.x + qcx;
            float gcy = Sc.y + Pc.y + qcy;
            if (ii >= 0) {
                accx += sigmoidf_(gfx) * softplusf_(gcx);
                accy += sigmoidf_(gfy) * softplusf_(gcy);
            }
        }
    }
    float2 nin = *(const float2*)&nodein[(size_t)n * Ff + 2 * j];
    float2 o2;
    o2.x = softplusf_(fmaf(alpha, nin.x, accx));
    o2.y = softplusf_(fmaf(alpha, nin.y, accy));
    *(float2*)&dst[(size_t)n * Ff + 2 * j] = o2;
}

extern "C" void kernel_launch(void* const* d_in, const int* in_sizes, int n_in,
                              void* d_out, int out_size) {
    const float* nf  = (const float*)d_in[0];
    const float* ef  = (const float*)d_in[1];
    const int*   idx = (const int*)d_in[2];
    const float* Wn  = (const float*)d_in[3];
    const float* bn  = (const float*)d_in[4];
    const float* We  = (const float*)d_in[5];
    const float* be  = (const float*)d_in[6];
    const float* W[3] = {(const float*)d_in[7], (const float*)d_in[10], (const float*)d_in[13]};
    const float* b[3] = {(const float*)d_in[8], (const float*)d_in[11], (const float*)d_in[14]};
    const float* a[3] = {(const float*)d_in[9], (const float*)d_in[12], (const float*)d_in[15]};
    float* out = (float*)d_out;

    k_node_in<<<Nn / 8, 256>>>(nf, Wn, bn);              // -> g_bufA
    k_fold<<<3, 128>>>(We, be, W[0], W[1], W[2]);        // -> g_U, g_dv

    // layer 1: A -> B
    k_SP<<<Nn / 16, 256>>>(0, W[0], b[0], 0);
    k_conv<<<Nn / 4, 128>>>(0, 1, ef, idx, a[0], out, 0);
    // layer 2: B -> A
    k_SP<<<Nn / 16, 256>>>(1, W[1], b[1], 1);
    k_conv<<<Nn / 4, 128>>>(1, 0, ef, idx, a[1], out, 1);
    // layer 3: A -> d_out
    k_SP<<<Nn / 16, 256>>>(0, W[2], b[2], 2);
    k_conv<<<Nn / 4, 128>>>(0, 2, ef, idx, a[2], out, 2);
}